// round 3
// baseline (speedup 1.0000x reference)
#include <cuda_runtime.h>
#include <cuda_bf16.h>
#include <cstdint>

// Problem constants (fixed shapes for this bench)
#define NSPLAT 6144
#define NCOL   1024     // 32*32 depth columns (depth is z-independent here)
#define ZPC    6        // splats per column
#define NCAM   6
#define NCH    32
#define IMH    80
#define IMW    80

#define LOWPASS 0.3f
#define NEARCLIP 0.2f

#define PREP_BLOCKS 12      // 12 * 512 = 6144 splats
#define K1_THREADS  512

// ---------------- device scratch ----------------
__device__ float4 g_p0[NCAM * NSPLAT];   // u, v, 0.5*ia, ib
__device__ float4 g_p1[NCAM * NSPLAT];   // 0.5*ic, op, sqrt(a), sqrt(c)
__device__ int g_order[NCAM * NSPLAT];

// ---------------- fused preprocess + sort ----------------
__global__ void __launch_bounds__(K1_THREADS)
prep_sort_kernel(const float* __restrict__ density,
                 const float* __restrict__ cam_rot,
                 const float* __restrict__ cam_trans,
                 const float* __restrict__ cam_intr,
                 const float* __restrict__ pc_xyz,
                 const float* __restrict__ scales,
                 const float* __restrict__ rots)
{
    int tid = threadIdx.x;

    if (blockIdx.x < PREP_BLOCKS) {
        // ---------- preprocess: one thread per splat, loop over cameras ----------
        int i = blockIdx.x * K1_THREADS + tid;

        float x = pc_xyz[3*i+0], y = pc_xyz[3*i+1], z = pc_xyz[3*i+2];

        // camera-independent: quaternion -> rotation, scaled
        float qw = rots[4*i+0], qx = rots[4*i+1], qy = rots[4*i+2], qz = rots[4*i+3];
        float s = expf(scales[i]);
        float M00 = s*(1.f - 2.f*(qy*qy + qz*qz)), M01 = s*(2.f*(qx*qy - qw*qz)), M02 = s*(2.f*(qx*qz + qw*qy));
        float M10 = s*(2.f*(qx*qy + qw*qz)), M11 = s*(1.f - 2.f*(qx*qx + qz*qz)), M12 = s*(2.f*(qy*qz - qw*qx));
        float M20 = s*(2.f*(qx*qz - qw*qy)), M21 = s*(2.f*(qy*qz + qw*qx)), M22 = s*(1.f - 2.f*(qx*qx + qy*qy));

        float d = density[i];
        float op0 = (d > 0.f) ? (d + log1pf(expf(-d))) : log1pf(expf(d));

        #pragma unroll
        for (int cam = 0; cam < NCAM; cam++) {
            const float* Rc = cam_rot + cam*9;
            float R0 = Rc[0], R1 = Rc[1], R2 = Rc[2];
            float R3 = Rc[3], R4 = Rc[4], R5 = Rc[5];
            float R6 = Rc[6], R7 = Rc[7], R8 = Rc[8];
            float t0 = cam_trans[cam*3+0], t1 = cam_trans[cam*3+1], t2 = cam_trans[cam*3+2];
            float fx = cam_intr[cam*4+0], fy = cam_intr[cam*4+1];
            float cx = cam_intr[cam*4+2], cy = cam_intr[cam*4+3];

            float camx = R0*x + R1*y + R2*z + t0;
            float camy = R3*x + R4*y + R5*z + t1;
            float camz = __fadd_rn(__fadd_rn(__fadd_rn(__fmul_rn(R6,x), __fmul_rn(R7,y)),
                                             __fmul_rn(R8,z)), t2);

            bool valid = camz > NEARCLIP;
            float tz = fmaxf(camz, 1e-6f);

            float u = fx*camx/tz + cx;
            float v = fy*camy/tz + cy;

            float j00 =  fx/tz;
            float j02 = -fx*camx/(tz*tz);
            float j11 =  fy/tz;
            float j12 = -fy*camy/(tz*tz);

            // A = J @ Rcw (2x3)
            float A00 = j00*R0 + j02*R6, A01 = j00*R1 + j02*R7, A02 = j00*R2 + j02*R8;
            float A10 = j11*R3 + j12*R6, A11 = j11*R4 + j12*R7, A12 = j11*R5 + j12*R8;

            // Bm = A @ M (2x3)
            float B00 = A00*M00 + A01*M10 + A02*M20;
            float B01 = A00*M01 + A01*M11 + A02*M21;
            float B02 = A00*M02 + A01*M12 + A02*M22;
            float B10 = A10*M00 + A11*M10 + A12*M20;
            float B11 = A10*M01 + A11*M11 + A12*M21;
            float B12 = A10*M02 + A11*M12 + A12*M22;

            float cov00 = B00*B00 + B01*B01 + B02*B02;
            float cov01 = B00*B10 + B01*B11 + B02*B12;
            float cov11 = B10*B10 + B11*B11 + B12*B12;

            float a  = cov00 + LOWPASS;
            float bb = cov01;
            float c  = cov11 + LOWPASS;
            float det = a*c - bb*bb;
            float ia =  c/det;
            float ib = -bb/det;
            float ic =  a/det;

            float op = valid ? op0 : 0.f;

            int o = cam*NSPLAT + i;
            g_p0[o] = make_float4(u, v, 0.5f*ia, ib);
            g_p1[o] = make_float4(0.5f*ic, op, sqrtf(a), sqrtf(c));
        }
    } else {
        // ---------- sort: one block per camera, self-computes column keys ----------
        __shared__ unsigned long long sk[NCOL];
        int cam = blockIdx.x - PREP_BLOCKS;

        const float* Rc = cam_rot + cam*9;
        float R6 = Rc[6], R7 = Rc[7], R8 = Rc[8];
        float t2 = cam_trans[cam*3+2];

        for (int col = tid; col < NCOL; col += K1_THREADS) {
            int i = col * ZPC;   // first splat of this column (same x,y for all 6)
            float x = pc_xyz[3*i+0], y = pc_xyz[3*i+1], z = pc_xyz[3*i+2];
            // bitwise-identical depth chain to the reference ordering
            float camz = __fadd_rn(__fadd_rn(__fadd_rn(__fmul_rn(R6,x), __fmul_rn(R7,y)),
                                             __fmul_rn(R8,z)), t2);
            bool valid = camz > NEARCLIP;
            float tz = fmaxf(camz, 1e-6f);
            float depth = valid ? tz : (tz + 1e6f);
            sk[col] = ((unsigned long long)__float_as_uint(depth) << 32) | (unsigned int)col;
        }
        __syncthreads();

        for (int k = 2; k <= NCOL; k <<= 1) {
            for (int j = k >> 1; j > 0; j >>= 1) {
                for (int i = tid; i < NCOL; i += K1_THREADS) {
                    int ixj = i ^ j;
                    if (ixj > i) {
                        unsigned long long av = sk[i], bv = sk[ixj];
                        bool up = ((i & k) == 0);
                        if (up ? (av > bv) : (av < bv)) { sk[i] = bv; sk[ixj] = av; }
                    }
                }
                __syncthreads();
            }
        }

        for (int r = tid; r < NCOL; r += K1_THREADS) {
            int col = (int)(sk[r] & 0xffffffffull);
            int obase = cam*NSPLAT + r*ZPC;
            int ibase = col*ZPC;
            #pragma unroll
            for (int kz = 0; kz < ZPC; kz++)
                g_order[obase + kz] = ibase + kz;
        }
    }
}

// ---------------- render: 16x16 pixel tile, 256 threads ----------------
#define CHUNK 256

__global__ void __launch_bounds__(256)
render_kernel(const float* __restrict__ feats, float* __restrict__ out)
{
    int cam = blockIdx.z;
    int tid = threadIdx.x;
    int tx = tid & 15, ty = tid >> 4;
    int px = blockIdx.x * 16 + tx;
    int py = blockIdx.y * 16 + ty;
    float fpx = (float)px, fpy = (float)py;

    float x0 = (float)(blockIdx.x * 16), x1 = x0 + 15.f;
    float y0 = (float)(blockIdx.y * 16), y1 = y0 + 15.f;

    __shared__ float4 spa[CHUNK], spb[CHUNK];
    __shared__ float4 sfeat[CHUNK * 8];   // XOR-swizzled [slot][8 float4]
    __shared__ int warpcnt[8];

    float T = 1.f;
    float acc[NCH];
    #pragma unroll
    for (int c = 0; c < NCH; c++) acc[c] = 0.f;

    const int* ord = g_order + cam*NSPLAT;
    const float4* gp0 = g_p0 + cam*NSPLAT;
    const float4* gp1 = g_p1 + cam*NSPLAT;
    int lane = tid & 31, warp = tid >> 5;

    for (int base = 0; base < NSPLAT; base += CHUNK) {
        int idx = ord[base + tid];
        float4 pa = gp0[idx];   // u, v, hia, ib
        float4 pb = gp1[idx];   // hic, op, ex, ey

        // conservative tile cull: alpha_max over tile >= ~1e-8
        bool keep = false;
        float op = pb.y;
        if (op > 1e-8f) {
            float t = __logf(op) + 19.0f;
            float s = sqrtf(2.f * t);
            float dxn = fmaxf(fmaxf(x0 - pa.x, pa.x - x1), 0.f);
            float dyn = fmaxf(fmaxf(y0 - pa.y, pa.y - y1), 0.f);
            keep = (dxn <= pb.z * s) && (dyn <= pb.w * s);
        }

        unsigned ball = __ballot_sync(0xffffffffu, keep);
        if (lane == 0) warpcnt[warp] = __popc(ball);
        __syncthreads();

        int off = 0, total = 0;
        #pragma unroll
        for (int wct = 0; wct < 8; wct++) {
            int cwc = warpcnt[wct];
            if (wct < warp) off += cwc;
            total += cwc;
        }

        if (keep) {
            int pos = off + __popc(ball & ((1u << lane) - 1u));
            spa[pos] = pa;
            spb[pos] = pb;
            const float4* fr = (const float4*)feats + idx * 8;
            int sw = pos & 7;
            #pragma unroll
            for (int k = 0; k < 8; k++)
                sfeat[pos*8 + (k ^ sw)] = fr[k];
        }
        __syncthreads();

        #pragma unroll 2
        for (int j = 0; j < total; j++) {
            float4 a = spa[j];
            float4 b = spb[j];
            float dx = fpx - a.x;
            float dy = fpy - a.y;
            float power = -(a.z*dx*dx + b.x*dy*dy + a.w*dx*dy);
            float g = __expf(fminf(power, 0.f));
            float alpha = fminf(b.y * g, 0.99f);
            float w = T * alpha;
            if (w > 1e-10f) {
                int jw = j & 7;
                #pragma unroll
                for (int k = 0; k < 8; k++) {
                    float4 f = sfeat[j*8 + (k ^ jw)];
                    acc[4*k+0] += w * f.x;
                    acc[4*k+1] += w * f.y;
                    acc[4*k+2] += w * f.z;
                    acc[4*k+3] += w * f.w;
                }
            }
            T *= (1.f - alpha);
        }

        if (!__syncthreads_or(T > 1e-5f)) break;
    }

    // out layout: (B=1, NC, C, H, W)
    #pragma unroll
    for (int c = 0; c < NCH; c++)
        out[((cam*NCH + c)*IMH + py)*IMW + px] = acc[c];
}

// ---------------- launch ----------------
extern "C" void kernel_launch(void* const* d_in, const int* in_sizes, int n_in,
                              void* d_out, int out_size)
{
    const float* vox_features = (const float*)d_in[0];
    const float* density      = (const float*)d_in[1];
    const float* cam_rot      = (const float*)d_in[2];
    const float* cam_trans    = (const float*)d_in[3];
    const float* cam_intr     = (const float*)d_in[4];
    const float* pc_xyz       = (const float*)d_in[5];
    const float* scales       = (const float*)d_in[6];
    const float* rots         = (const float*)d_in[7];
    float* out = (float*)d_out;

    prep_sort_kernel<<<PREP_BLOCKS + NCAM, K1_THREADS>>>(
        density, cam_rot, cam_trans, cam_intr, pc_xyz, scales, rots);

    dim3 rg(IMW / 16, IMH / 16, NCAM);
    render_kernel<<<rg, 256>>>(vox_features, out);
}

// round 4
// speedup vs baseline: 1.0060x; 1.0060x over previous
#include <cuda_runtime.h>
#include <cuda_bf16.h>
#include <cstdint>

// Problem constants (fixed shapes for this bench)
#define NSPLAT 6144
#define NCOL   1024     // 32*32 depth columns (depth is z-independent here)
#define ZPC    6        // splats per column
#define NCAM   6
#define NCH    32
#define IMH    80
#define IMW    80

#define LOWPASS 0.3f
#define NEARCLIP 0.2f

#define K1_THREADS  512
#define PREP_BLOCKS_PER_CAM 12     // 12 * 512 = 6144
#define PREP_BLOCKS (PREP_BLOCKS_PER_CAM * NCAM)   // 72

// ---------------- device scratch ----------------
__device__ float4 g_p0[NCAM * NSPLAT];   // u, v, 0.5*ia, ib
__device__ float4 g_p1[NCAM * NSPLAT];   // 0.5*ic, op, sqrt(a), sqrt(c)
__device__ int g_order[NCAM * NSPLAT];

// ---------------- fused preprocess + sort ----------------
__global__ void __launch_bounds__(K1_THREADS)
prep_sort_kernel(const float* __restrict__ density,
                 const float* __restrict__ cam_rot,
                 const float* __restrict__ cam_trans,
                 const float* __restrict__ cam_intr,
                 const float* __restrict__ pc_xyz,
                 const float* __restrict__ scales,
                 const float* __restrict__ rots)
{
    int tid = threadIdx.x;

    if (blockIdx.x < PREP_BLOCKS) {
        // ---------- preprocess: one thread per (cam, splat) ----------
        int cam = blockIdx.x / PREP_BLOCKS_PER_CAM;
        int i   = (blockIdx.x % PREP_BLOCKS_PER_CAM) * K1_THREADS + tid;

        float x = pc_xyz[3*i+0], y = pc_xyz[3*i+1], z = pc_xyz[3*i+2];

        const float* Rc = cam_rot + cam*9;
        float R0 = Rc[0], R1 = Rc[1], R2 = Rc[2];
        float R3 = Rc[3], R4 = Rc[4], R5 = Rc[5];
        float R6 = Rc[6], R7 = Rc[7], R8 = Rc[8];
        float t0 = cam_trans[cam*3+0], t1 = cam_trans[cam*3+1], t2 = cam_trans[cam*3+2];
        float fx = cam_intr[cam*4+0], fy = cam_intr[cam*4+1];
        float cx = cam_intr[cam*4+2], cy = cam_intr[cam*4+3];

        float camx = R0*x + R1*y + R2*z + t0;
        float camy = R3*x + R4*y + R5*z + t1;
        // depth: no fma contraction, left-to-right, to reproduce exact tie groups
        float camz = __fadd_rn(__fadd_rn(__fadd_rn(__fmul_rn(R6,x), __fmul_rn(R7,y)),
                                         __fmul_rn(R8,z)), t2);

        bool valid = camz > NEARCLIP;
        float tz = fmaxf(camz, 1e-6f);

        float u = fx*camx/tz + cx;
        float v = fy*camy/tz + cy;

        float j00 =  fx/tz;
        float j02 = -fx*camx/(tz*tz);
        float j11 =  fy/tz;
        float j12 = -fy*camy/(tz*tz);

        // quaternion -> rotation (scaled)
        float qw = rots[4*i+0], qx = rots[4*i+1], qy = rots[4*i+2], qz = rots[4*i+3];
        float s = expf(scales[i]);
        float M00 = s*(1.f - 2.f*(qy*qy + qz*qz)), M01 = s*(2.f*(qx*qy - qw*qz)), M02 = s*(2.f*(qx*qz + qw*qy));
        float M10 = s*(2.f*(qx*qy + qw*qz)), M11 = s*(1.f - 2.f*(qx*qx + qz*qz)), M12 = s*(2.f*(qy*qz - qw*qx));
        float M20 = s*(2.f*(qx*qz - qw*qy)), M21 = s*(2.f*(qy*qz + qw*qx)), M22 = s*(1.f - 2.f*(qx*qx + qy*qy));

        // A = J @ Rcw (2x3)
        float A00 = j00*R0 + j02*R6, A01 = j00*R1 + j02*R7, A02 = j00*R2 + j02*R8;
        float A10 = j11*R3 + j12*R6, A11 = j11*R4 + j12*R7, A12 = j11*R5 + j12*R8;

        // Bm = A @ M (2x3)
        float B00 = A00*M00 + A01*M10 + A02*M20;
        float B01 = A00*M01 + A01*M11 + A02*M21;
        float B02 = A00*M02 + A01*M12 + A02*M22;
        float B10 = A10*M00 + A11*M10 + A12*M20;
        float B11 = A10*M01 + A11*M11 + A12*M21;
        float B12 = A10*M02 + A11*M12 + A12*M22;

        float cov00 = B00*B00 + B01*B01 + B02*B02;
        float cov01 = B00*B10 + B01*B11 + B02*B12;
        float cov11 = B10*B10 + B11*B11 + B12*B12;

        float a  = cov00 + LOWPASS;
        float bb = cov01;
        float c  = cov11 + LOWPASS;
        float det = a*c - bb*bb;
        float ia =  c/det;
        float ib = -bb/det;
        float ic =  a/det;

        float d = density[i];
        float op = (d > 0.f) ? (d + log1pf(expf(-d))) : log1pf(expf(d));
        if (!valid) op = 0.f;

        int o = cam*NSPLAT + i;
        g_p0[o] = make_float4(u, v, 0.5f*ia, ib);
        g_p1[o] = make_float4(0.5f*ic, op, sqrtf(a), sqrtf(c));
    } else {
        // ---------- sort: one block per camera, self-computes column keys ----------
        __shared__ unsigned long long sk[NCOL];
        int cam = blockIdx.x - PREP_BLOCKS;

        const float* Rc = cam_rot + cam*9;
        float R6 = Rc[6], R7 = Rc[7], R8 = Rc[8];
        float t2 = cam_trans[cam*3+2];

        for (int col = tid; col < NCOL; col += K1_THREADS) {
            int i = col * ZPC;   // first splat of this column (same x,y for all 6)
            float x = pc_xyz[3*i+0], y = pc_xyz[3*i+1], z = pc_xyz[3*i+2];
            // bitwise-identical depth chain to the reference ordering
            float camz = __fadd_rn(__fadd_rn(__fadd_rn(__fmul_rn(R6,x), __fmul_rn(R7,y)),
                                             __fmul_rn(R8,z)), t2);
            bool valid = camz > NEARCLIP;
            float tz = fmaxf(camz, 1e-6f);
            float depth = valid ? tz : (tz + 1e6f);
            sk[col] = ((unsigned long long)__float_as_uint(depth) << 32) | (unsigned int)col;
        }
        __syncthreads();

        for (int k = 2; k <= NCOL; k <<= 1) {
            for (int j = k >> 1; j > 0; j >>= 1) {
                for (int i = tid; i < NCOL; i += K1_THREADS) {
                    int ixj = i ^ j;
                    if (ixj > i) {
                        unsigned long long av = sk[i], bv = sk[ixj];
                        bool up = ((i & k) == 0);
                        if (up ? (av > bv) : (av < bv)) { sk[i] = bv; sk[ixj] = av; }
                    }
                }
                __syncthreads();
            }
        }

        for (int r = tid; r < NCOL; r += K1_THREADS) {
            int col = (int)(sk[r] & 0xffffffffull);
            int obase = cam*NSPLAT + r*ZPC;
            int ibase = col*ZPC;
            #pragma unroll
            for (int kz = 0; kz < ZPC; kz++)
                g_order[obase + kz] = ibase + kz;
        }
    }
}

// ---------------- render: 16x16 pixel tile, 256 threads ----------------
#define CHUNK 256

__device__ __forceinline__ void ffma2(unsigned long long &acc,
                                      unsigned long long f,
                                      unsigned long long w2)
{
    asm("fma.rn.f32x2 %0, %1, %2, %0;" : "+l"(acc) : "l"(f), "l"(w2));
}

__global__ void __launch_bounds__(256)
render_kernel(const float* __restrict__ feats, float* __restrict__ out)
{
    int cam = blockIdx.z;
    int tid = threadIdx.x;
    int tx = tid & 15, ty = tid >> 4;
    int px = blockIdx.x * 16 + tx;
    int py = blockIdx.y * 16 + ty;
    float fpx = (float)px, fpy = (float)py;

    float x0 = (float)(blockIdx.x * 16), x1 = x0 + 15.f;
    float y0 = (float)(blockIdx.y * 16), y1 = y0 + 15.f;

    __shared__ float4 spa[CHUNK];          // u, v, hia, ib
    __shared__ float2 spb[CHUNK];          // hic, op
    __shared__ float4 sfeat[CHUNK * 8];    // XOR-swizzled [slot][8 float4]
    __shared__ int warpcnt[8];

    float T = 1.f;
    unsigned long long acc[NCH/2];
    #pragma unroll
    for (int k = 0; k < NCH/2; k++) acc[k] = 0ull;

    const int* ord = g_order + cam*NSPLAT;
    const float4* gp0 = g_p0 + cam*NSPLAT;
    const float4* gp1 = g_p1 + cam*NSPLAT;
    int lane = tid & 31, warp = tid >> 5;

    for (int base = 0; base < NSPLAT; base += CHUNK) {
        int idx = ord[base + tid];
        float4 pa = gp0[idx];   // u, v, hia, ib
        float4 pb = gp1[idx];   // hic, op, ex, ey

        // conservative tile cull: alpha_max over tile >= ~1e-8
        bool keep = false;
        float op = pb.y;
        if (op > 1e-8f) {
            float t = __logf(op) + 19.0f;
            float s = sqrtf(2.f * t);
            float dxn = fmaxf(fmaxf(x0 - pa.x, pa.x - x1), 0.f);
            float dyn = fmaxf(fmaxf(y0 - pa.y, pa.y - y1), 0.f);
            keep = (dxn <= pb.z * s) && (dyn <= pb.w * s);
        }

        unsigned ball = __ballot_sync(0xffffffffu, keep);
        if (lane == 0) warpcnt[warp] = __popc(ball);
        __syncthreads();

        int off = 0, total = 0;
        #pragma unroll
        for (int wct = 0; wct < 8; wct++) {
            int cwc = warpcnt[wct];
            if (wct < warp) off += cwc;
            total += cwc;
        }

        if (keep) {
            int pos = off + __popc(ball & ((1u << lane) - 1u));
            spa[pos] = pa;
            spb[pos] = make_float2(pb.x, pb.y);
            const float4* fr = (const float4*)feats + idx * 8;
            int sw = pos & 7;
            #pragma unroll
            for (int k = 0; k < 8; k++)
                sfeat[pos*8 + (k ^ sw)] = fr[k];
        }
        __syncthreads();

        // whole-warp skip when every lane is saturated (error <= T <= 1e-5)
        if (__any_sync(0xffffffffu, T > 1e-5f)) {
            #pragma unroll 2
            for (int j = 0; j < total; j++) {
                float4 a = spa[j];
                float2 b = spb[j];
                float dx = fpx - a.x;
                float dy = fpy - a.y;
                float power = -(a.z*dx*dx + b.x*dy*dy + a.w*dx*dy);
                float g = __expf(fminf(power, 0.f));
                float alpha = fminf(b.y * g, 0.99f);
                float w = T * alpha;
                if (w > 1e-10f) {
                    unsigned long long w2;
                    asm("mov.b64 %0, {%1, %1};" : "=l"(w2) : "f"(w));
                    int jw = j & 7;
                    #pragma unroll
                    for (int m = 0; m < 8; m++) {
                        ulonglong2 f = *(const ulonglong2*)&sfeat[j*8 + (m ^ jw)];
                        ffma2(acc[2*m],   f.x, w2);
                        ffma2(acc[2*m+1], f.y, w2);
                    }
                }
                T *= (1.f - alpha);
            }
        }

        if (!__syncthreads_or(T > 1e-5f)) break;
    }

    // out layout: (B=1, NC, C, H, W); acc[k] = channels (2k, 2k+1)
    #pragma unroll
    for (int k = 0; k < NCH/2; k++) {
        float lo, hi;
        asm("mov.b64 {%0, %1}, %2;" : "=f"(lo), "=f"(hi) : "l"(acc[k]));
        out[((cam*NCH + 2*k  )*IMH + py)*IMW + px] = lo;
        out[((cam*NCH + 2*k+1)*IMH + py)*IMW + px] = hi;
    }
}

// ---------------- launch ----------------
extern "C" void kernel_launch(void* const* d_in, const int* in_sizes, int n_in,
                              void* d_out, int out_size)
{
    const float* vox_features = (const float*)d_in[0];
    const float* density      = (const float*)d_in[1];
    const float* cam_rot      = (const float*)d_in[2];
    const float* cam_trans    = (const float*)d_in[3];
    const float* cam_intr     = (const float*)d_in[4];
    const float* pc_xyz       = (const float*)d_in[5];
    const float* scales       = (const float*)d_in[6];
    const float* rots         = (const float*)d_in[7];
    float* out = (float*)d_out;

    prep_sort_kernel<<<PREP_BLOCKS + NCAM, K1_THREADS>>>(
        density, cam_rot, cam_trans, cam_intr, pc_xyz, scales, rots);

    dim3 rg(IMW / 16, IMH / 16, NCAM);
    render_kernel<<<rg, 256>>>(vox_features, out);
}